// round 5
// baseline (speedup 1.0000x reference)
#include <cuda_runtime.h>
#include <cstdint>

#define NB_B 8192
#define LOD 60
#define LSD 120
#define AD 10
#define NB 15
#define HH 60
#define BX 64
#define BY 15
#define NT 960

typedef unsigned long long u64;

// ---- device scratch ----
__device__ float4 g_tmb[LOD * 7 * NB];     // (t11,t21,t12,t22) banded, k fastest
__device__ float  g_coef[NB * NB_B];       // softmax coefs [k][b]
__device__ float  g_ctlT[NB_B * LSD];      // control, row-major [b][c]
__device__ float  g_tc[LSD];               // elup1(log_noise)

#define FMA2(acc, a, b) asm("fma.rn.f32x2 %0, %1, %2, %0;" : "+l"(acc) : "l"(a), "l"(b))
__device__ __forceinline__ float2 U2F(u64 v){ float2 r; asm("mov.b64 {%0,%1},%2;" : "=f"(r.x), "=f"(r.y) : "l"(v)); return r; }
__device__ __forceinline__ u64 F2U(float x, float y){ u64 r; asm("mov.b64 %0,{%1,%2};" : "=l"(r) : "f"(x), "f"(y)); return r; }
__device__ __forceinline__ u64 LDS64(uint32_t a){ u64 r; asm("ld.shared.b64 %0,[%1];" : "=l"(r) : "r"(a)); return r; }

// ======================= prep kernel =======================
// blocks 0..255: coef softmax + control MLP, 32 batch each, block (32,16)
// blocks 256..268: tmb pack (+ tc on 256)
#define PAD 33
#define PP_PM  0        // 120*33 = 3960 ; reused as ctl stage
#define PP_LG  3960     // 15*33 = 495
#define PP_ACT 4455     // 10*33 = 330
#define PP_H   4785     // 60*33 = 1980
#define PP_WC  6765     // 1800
#define PP_W1  8565     // 600
#define PP_W2  9165     // 7200
#define PP_B1  16365    // 60
#define PP_B2  16425    // 120
#define PP_BC  16545    // 15
#define PP_SMEM 16560

__global__ void __launch_bounds__(512, 2) prep_kernel(
    const float* __restrict__ post_mean, const float* __restrict__ action,
    const float* __restrict__ tm11, const float* __restrict__ tm12,
    const float* __restrict__ tm21, const float* __restrict__ tm22,
    const float* __restrict__ log_noise,
    const float* __restrict__ w_coef, const float* __restrict__ b_coef,
    const float* __restrict__ w_c1, const float* __restrict__ b_c1,
    const float* __restrict__ w_c2, const float* __restrict__ b_c2)
{
    const int bid = blockIdx.x;
    const int bl = threadIdx.x;          // 0..31
    const int yy = threadIdx.y;          // 0..15
    const int tid = yy * 32 + bl;

    if (bid >= 256) {                    // tmb pack + tc
        if (bid == 256 && tid < LSD) {
            float x = log_noise[tid];
            g_tc[tid] = (x < 0.f) ? expf(x) : x + 1.f;
        }
        int idx = (bid - 256) * 512 + tid;
        if (idx < LOD * 7 * NB) {
            int k = idx % NB;
            int jj = (idx / NB) % 7;
            int i = idx / (NB * 7);
            int j = i + jj - 3;
            float4 v = make_float4(0.f, 0.f, 0.f, 0.f);
            if (j >= 0 && j < LOD) {
                int off = k * LOD * LOD + i * LOD + j;
                v.x = tm11[off]; v.y = tm21[off];
                v.z = tm12[off]; v.w = tm22[off];
            }
            g_tmb[idx] = v;
        }
        return;
    }

    extern __shared__ float sp[];
    const int b0 = bid * 32;

    for (int e = tid; e < 32 * LSD; e += 512) {
        int b = e / LSD, d = e % LSD;
        sp[PP_PM + d * PAD + b] = post_mean[(b0 + b) * LSD + d];
    }
    for (int e = tid; e < 32 * AD; e += 512) {
        int b = e / AD, d = e % AD;
        sp[PP_ACT + d * PAD + b] = action[(b0 + b) * AD + d];
    }
    for (int e = tid; e < NB * LSD; e += 512) sp[PP_WC + e] = w_coef[e];
    for (int e = tid; e < HH * AD; e += 512)  sp[PP_W1 + e] = w_c1[e];
    for (int e = tid; e < LSD * HH; e += 512) sp[PP_W2 + e] = w_c2[e];
    if (tid < HH)  sp[PP_B1 + tid] = b_c1[tid];
    if (tid < LSD) sp[PP_B2 + tid] = b_c2[tid];
    if (tid < NB)  sp[PP_BC + tid] = b_coef[tid];
    __syncthreads();

    // logits (one k per y row)
    if (yy < NB) {
        float lg = sp[PP_BC + yy];
        #pragma unroll 4
        for (int d = 0; d < LSD; d++)
            lg = fmaf(sp[PP_WC + yy * LSD + d], sp[PP_PM + d * PAD + bl], lg);
        sp[PP_LG + yy * PAD + bl] = lg;
    }
    // hidden layer
    #pragma unroll
    for (int t = 0; t < 4; t++) {
        int i = yy + 16 * t;
        if (i < HH) {
            float hv = sp[PP_B1 + i];
            #pragma unroll
            for (int d = 0; d < AD; d++)
                hv = fmaf(sp[PP_W1 + i * AD + d], sp[PP_ACT + d * PAD + bl], hv);
            sp[PP_H + i * PAD + bl] = fmaxf(hv, 0.f);
        }
    }
    __syncthreads();

    // softmax per batch element (warp 0)
    if (yy == 0) {
        float mx = -1e30f;
        #pragma unroll
        for (int k = 0; k < NB; k++) mx = fmaxf(mx, sp[PP_LG + k * PAD + bl]);
        float ex[NB], sum = 0.f;
        #pragma unroll
        for (int k = 0; k < NB; k++) {
            ex[k] = expf(sp[PP_LG + k * PAD + bl] - mx);
            sum += ex[k];
        }
        float inv = 1.f / sum;
        #pragma unroll
        for (int k = 0; k < NB; k++)
            g_coef[k * NB_B + b0 + bl] = ex[k] * inv;
    }
    // control output -> stage into PM region (dead now)
    #pragma unroll
    for (int t = 0; t < 8; t++) {
        int c = yy + 16 * t;
        if (c < LSD) {
            float ctl = sp[PP_B2 + c];
            #pragma unroll 4
            for (int m = 0; m < HH; m++)
                ctl = fmaf(sp[PP_W2 + c * HH + m], sp[PP_H + m * PAD + bl], ctl);
            sp[PP_PM + c * PAD + bl] = ctl;
        }
    }
    __syncthreads();

    // coalesced transposed store of control
    for (int e = tid; e < 32 * LSD; e += 512) {
        int b = e / LSD, c = e % LSD;
        g_ctlT[(b0 + b) * LSD + c] = sp[PP_PM + c * PAD + b];
    }
}

// ======================= main kernel =======================
// smem float offsets
#define SM_TMB   0        // 25200 floats; reused as stage[300*67] = 20100
#define SM_MUML  25200    // float2[60][66] -> 7920 floats
#define SM_CUCL  33120    // 7920
#define SM_CS2   41040    // 3960
#define SM_COEF  45000    // u64[15][64] -> 1920 floats
#define SM_TC    46920    // 120
#define SM_FLOATS 47040   // 188160 bytes

template<int J0, int JN>
__device__ __forceinline__ void mix_pass(
    uint32_t tmbRow, uint32_t coefA, u64* aX, u64* aY)
{
    #pragma unroll
    for (int jj = 0; jj < JN; jj++) { aX[jj] = 0; aY[jj] = 0; }
    #pragma unroll
    for (int k = 0; k < NB; k++) {
        u64 c2 = LDS64(coefA + (uint32_t)(k * 512));
        #pragma unroll
        for (int jj = 0; jj < JN; jj++) {
            u64 vX, vY;   // (t11,t21), (t12,t22) — warp-uniform broadcast
            asm("ld.shared.v2.u64 {%0,%1},[%2];"
                : "=l"(vX), "=l"(vY)
                : "r"(tmbRow + (uint32_t)(((J0 + jj) * NB + k) * 16)));
            FMA2(aX[jj], c2, vX);
            FMA2(aY[jj], c2, vY);
        }
    }
}

__device__ __forceinline__ void combine(
    u64 aXv, u64 aYv, bool diag, int jc, int x, const float* __restrict__ sm,
    float& nmu, float& nml, float& ncu, float& ncl, float& ncs)
{
    float2 X = U2F(aXv), Y = U2F(aYv);
    float t11 = X.x, t21 = X.y, t12 = Y.x, t22 = Y.y;
    if (diag) { t11 += 1.f; t22 += 1.f; }
    float2 mm = ((const float2*)(sm + SM_MUML))[jc * 66 + x];   // (mu, ml)
    float2 cc = ((const float2*)(sm + SM_CUCL))[jc * 66 + x];   // (cu, cl)
    float cs2 = sm[SM_CS2 + jc * 66 + x];
    nmu = fmaf(t11, mm.x, fmaf(t12, mm.y, nmu));
    nml = fmaf(t21, mm.x, fmaf(t22, mm.y, nml));
    ncu = fmaf(t11 * t11, cc.x, fmaf(t11 * t12, cs2, fmaf(t12 * t12, cc.y, ncu)));
    ncl = fmaf(t21 * t21, cc.x, fmaf(t21 * t22, cs2, fmaf(t22 * t22, cc.y, ncl)));
    ncs = fmaf(t21 * t11, cc.x,
          fmaf(0.5f * fmaf(t22, t11, t21 * t12), cs2,
          fmaf(t22 * t12, cc.y, ncs)));
}

__global__ void __launch_bounds__(NT, 1) acpredict_kernel(
    const float* __restrict__ post_mean, const float* __restrict__ cu_g,
    const float* __restrict__ cl_g, const float* __restrict__ cs_g,
    float* __restrict__ out)
{
    extern __shared__ float sm[];
    const int x   = threadIdx.x;           // 0..63 : batch element
    const int y   = threadIdx.y;           // 0..14 : row group
    const int tid = y * BX + x;
    const int b0  = blockIdx.x * BX;

    // ---- loads ----
    {
        float4* t4 = (float4*)sm;
        for (int e = tid; e < LOD * 7 * NB; e += NT) t4[e] = g_tmb[e];
    }
    for (int e = tid; e < BX * LSD; e += NT) {
        int bl = e / LSD, d = e % LSD;
        float v = post_mean[(b0 + bl) * LSD + d];
        int j = (d < LOD) ? d : d - LOD;
        sm[SM_MUML + (j * 66 + bl) * 2 + (d < LOD ? 0 : 1)] = v;
    }
    for (int e = tid; e < BX * LOD; e += NT) {
        int bl = e / LOD, j = e % LOD;
        sm[SM_CUCL + (j * 66 + bl) * 2 + 0] = cu_g[(b0 + bl) * LOD + j];
        sm[SM_CUCL + (j * 66 + bl) * 2 + 1] = cl_g[(b0 + bl) * LOD + j];
        sm[SM_CS2 + j * 66 + bl] = 2.f * cs_g[(b0 + bl) * LOD + j];
    }
    for (int e = tid; e < NB * BX; e += NT) {
        int k = e / BX, bl = e % BX;
        float c = g_coef[k * NB_B + b0 + bl];
        ((u64*)(sm + SM_COEF))[k * BX + bl] = F2U(c, c);
    }
    if (tid < LSD) sm[SM_TC + tid] = g_tc[tid];
    __syncthreads();

    const uint32_t sbase = (uint32_t)__cvta_generic_to_shared(sm);
    const uint32_t coefA = sbase + SM_COEF * 4 + (uint32_t)x * 8u;

    float res[4][5];

    #pragma unroll
    for (int t = 0; t < 4; t++) {
        const int i = y + BY * t;
        const uint32_t tmbRow = sbase + (uint32_t)(i * 7 * NB * 16);
        float nmu = 0.f, nml = 0.f, ncu = 0.f, ncl = 0.f, ncs = 0.f;
        {   // jj 0..3
            u64 aX[4], aY[4];
            mix_pass<0, 4>(tmbRow, coefA, aX, aY);
            #pragma unroll
            for (int jj = 0; jj < 4; jj++) {
                int jc = max(i + jj - 3, 0);
                combine(aX[jj], aY[jj], jj == 3, jc, x, sm, nmu, nml, ncu, ncl, ncs);
            }
        }
        {   // jj 4..6
            u64 aX[3], aY[3];
            mix_pass<4, 3>(tmbRow, coefA, aX, aY);
            #pragma unroll
            for (int jj = 0; jj < 3; jj++) {
                int jc = min(i + 1 + jj, LOD - 1);
                combine(aX[jj], aY[jj], false, jc, x, sm, nmu, nml, ncu, ncl, ncs);
            }
        }
        res[t][0] = nmu; res[t][1] = nml;
        res[t][2] = ncu; res[t][3] = ncl; res[t][4] = ncs;
    }

    __syncthreads();                 // all tmb/input reads complete
    #pragma unroll
    for (int t = 0; t < 4; t++) {    // stage into dead tmb region, stride 67
        int i = y + BY * t;
        sm[(i)        * 67 + x] = res[t][0];
        sm[(LOD + i)  * 67 + x] = res[t][1];
        sm[(120 + i)  * 67 + x] = res[t][2];
        sm[(180 + i)  * 67 + x] = res[t][3];
        sm[(240 + i)  * 67 + x] = res[t][4];
    }
    __syncthreads();

    // ---- coalesced stores; fold in control + trans_cov here ----
    for (int e = tid; e < BX * 300; e += NT) {
        int bl = e / 300, c = e % 300;
        float v = sm[c * 67 + bl];
        int bb = b0 + bl;
        if (c < 120) {
            v += __ldg(&g_ctlT[bb * LSD + c]);
            out[bb * 120 + c] = v;
        } else {
            if (c < 240) v += sm[SM_TC + (c - 120)];
            int blk = c / 60;        // 2, 3, 4
            out[NB_B * 60 * blk + bb * 60 + (c - blk * 60)] = v;
        }
    }
}

extern "C" void kernel_launch(void* const* d_in, const int* in_sizes, int n_in,
                              void* d_out, int out_size) {
    const float* post_mean = (const float*)d_in[0];
    const float* cu        = (const float*)d_in[1];
    const float* cl        = (const float*)d_in[2];
    const float* cs        = (const float*)d_in[3];
    const float* action    = (const float*)d_in[4];
    const float* tm11      = (const float*)d_in[5];
    const float* tm12      = (const float*)d_in[6];
    const float* tm21      = (const float*)d_in[7];
    const float* tm22      = (const float*)d_in[8];
    const float* log_noise = (const float*)d_in[9];
    const float* w_coef    = (const float*)d_in[10];
    const float* b_coef    = (const float*)d_in[11];
    const float* w_c1      = (const float*)d_in[12];
    const float* b_c1      = (const float*)d_in[13];
    const float* w_c2      = (const float*)d_in[14];
    const float* b_c2      = (const float*)d_in[15];
    float* out = (float*)d_out;

    static bool attr_done = false;
    if (!attr_done) {
        cudaFuncSetAttribute(prep_kernel,
            cudaFuncAttributeMaxDynamicSharedMemorySize, PP_SMEM * 4);
        cudaFuncSetAttribute(acpredict_kernel,
            cudaFuncAttributeMaxDynamicSharedMemorySize, SM_FLOATS * 4);
        attr_done = true;
    }

    dim3 pblk(32, 16);
    prep_kernel<<<256 + 13, pblk, PP_SMEM * 4>>>(
        post_mean, action, tm11, tm12, tm21, tm22, log_noise,
        w_coef, b_coef, w_c1, b_c1, w_c2, b_c2);

    dim3 blk(BX, BY);
    acpredict_kernel<<<NB_B / BX, blk, SM_FLOATS * 4>>>(post_mean, cu, cl, cs, out);
}

// round 6
// speedup vs baseline: 1.0718x; 1.0718x over previous
#include <cuda_runtime.h>
#include <cstdint>

#define NB_B 8192
#define LOD 60
#define LSD 120
#define AD 10
#define NB 15
#define HH 60
#define BX 64
#define BY 12
#define NT 768

typedef unsigned long long u64;

// ---- device scratch ----
__device__ float4 g_tmb[LOD * 7 * NB];     // (t11,t21,t12,t22) banded, k fastest

#define FMA2(acc, a, b) asm("fma.rn.f32x2 %0, %1, %2, %0;" : "+l"(acc) : "l"(a), "l"(b))
__device__ __forceinline__ float2 U2F(u64 v){ float2 r; asm("mov.b64 {%0,%1},%2;" : "=f"(r.x), "=f"(r.y) : "l"(v)); return r; }
__device__ __forceinline__ u64 F2U(float x, float y){ u64 r; asm("mov.b64 %0,{%1,%2};" : "=l"(r) : "f"(x), "f"(y)); return r; }
__device__ __forceinline__ u64 LDS64(uint32_t a){ u64 r; asm("ld.shared.b64 %0,[%1];" : "=l"(r) : "r"(a)); return r; }

// ======================= pack kernel (tiny, overlapped via PDL) =======================
__global__ void __launch_bounds__(512) pack_kernel(
    const float* __restrict__ tm11, const float* __restrict__ tm12,
    const float* __restrict__ tm21, const float* __restrict__ tm22)
{
    int idx = blockIdx.x * 512 + threadIdx.x;
    if (idx >= LOD * 7 * NB) return;
    int k = idx % NB;
    int jj = (idx / NB) % 7;
    int i = idx / (NB * 7);
    int j = i + jj - 3;
    float4 v = make_float4(0.f, 0.f, 0.f, 0.f);
    if (j >= 0 && j < LOD) {
        int off = k * LOD * LOD + i * LOD + j;
        v.x = tm11[off]; v.y = tm21[off];
        v.z = tm12[off]; v.w = tm22[off];
    }
    g_tmb[idx] = v;
}

// ======================= fused main kernel =======================
// persistent smem regions (float offsets)
#define SM_TMB   0        // 25200 floats; holds prep scratch first, then tmb, then stage[300*67]
#define SM_MUML  25200    // float2[60][66] -> 7920
#define SM_CUCL  33120    // 7920
#define SM_CS2   41040    // 3960
#define SM_COEF  45000    // u64[15][64] -> 1920
#define SM_TC    46920    // 120
#define SM_CTL   47040    // [120][66] -> 7920
#define SM_FLOATS 54960   // 219840 bytes

// prep scratch inside tmb region (dead before tmb load)
#define PW_WC  0          // 1800
#define PW_W1  1800       // 600
#define PW_W2  2400       // 7200
#define PW_B1  9600       // 60
#define PW_B2  9660       // 120
#define PW_BC  9780       // 15 (+pad)
#define PW_ACT 9800       // 10*66
#define PW_H   10460      // 60*66
#define PW_LG  14420      // 15*66 -> end 15410 < 25200

template<int J0, int JN>
__device__ __forceinline__ void mix_pass(
    uint32_t tmbRow, uint32_t coefA, u64* aX, u64* aY)
{
    #pragma unroll
    for (int jj = 0; jj < JN; jj++) { aX[jj] = 0; aY[jj] = 0; }
    #pragma unroll
    for (int k = 0; k < NB; k++) {
        u64 c2 = LDS64(coefA + (uint32_t)(k * 512));
        #pragma unroll
        for (int jj = 0; jj < JN; jj++) {
            u64 vX, vY;   // (t11,t21), (t12,t22) — warp-uniform broadcast
            asm("ld.shared.v2.u64 {%0,%1},[%2];"
                : "=l"(vX), "=l"(vY)
                : "r"(tmbRow + (uint32_t)(((J0 + jj) * NB + k) * 16)));
            FMA2(aX[jj], c2, vX);
            FMA2(aY[jj], c2, vY);
        }
    }
}

__device__ __forceinline__ void combine(
    u64 aXv, u64 aYv, bool diag, int jc, int x, const float* __restrict__ sm,
    float& nmu, float& nml, float& ncu, float& ncl, float& ncs)
{
    float2 X = U2F(aXv), Y = U2F(aYv);
    float t11 = X.x, t21 = X.y, t12 = Y.x, t22 = Y.y;
    if (diag) { t11 += 1.f; t22 += 1.f; }
    float2 mm = ((const float2*)(sm + SM_MUML))[jc * 66 + x];   // (mu, ml)
    float2 cc = ((const float2*)(sm + SM_CUCL))[jc * 66 + x];   // (cu, cl)
    float cs2 = sm[SM_CS2 + jc * 66 + x];
    nmu = fmaf(t11, mm.x, fmaf(t12, mm.y, nmu));
    nml = fmaf(t21, mm.x, fmaf(t22, mm.y, nml));
    ncu = fmaf(t11 * t11, cc.x, fmaf(t11 * t12, cs2, fmaf(t12 * t12, cc.y, ncu)));
    ncl = fmaf(t21 * t21, cc.x, fmaf(t21 * t22, cs2, fmaf(t22 * t22, cc.y, ncl)));
    ncs = fmaf(t21 * t11, cc.x,
          fmaf(0.5f * fmaf(t22, t11, t21 * t12), cs2,
          fmaf(t22 * t12, cc.y, ncs)));
}

__global__ void __launch_bounds__(NT, 1) acpredict_kernel(
    const float* __restrict__ post_mean, const float* __restrict__ cu_g,
    const float* __restrict__ cl_g, const float* __restrict__ cs_g,
    const float* __restrict__ action, const float* __restrict__ log_noise,
    const float* __restrict__ w_coef, const float* __restrict__ b_coef,
    const float* __restrict__ w_c1, const float* __restrict__ b_c1,
    const float* __restrict__ w_c2, const float* __restrict__ b_c2,
    float* __restrict__ out)
{
    extern __shared__ float sm[];
    const int x   = threadIdx.x;           // 0..63 : batch element
    const int y   = threadIdx.y;           // 0..11 : row group
    const int tid = y * BX + x;
    const int b0  = blockIdx.x * BX;

    // ---- phase 0: load inputs + prep weights (tmb region holds scratch) ----
    for (int e = tid; e < BX * LSD; e += NT) {
        int bl = e / LSD, d = e % LSD;
        float v = post_mean[(b0 + bl) * LSD + d];
        int j = (d < LOD) ? d : d - LOD;
        sm[SM_MUML + (j * 66 + bl) * 2 + (d < LOD ? 0 : 1)] = v;
    }
    for (int e = tid; e < BX * LOD; e += NT) {
        int bl = e / LOD, j = e % LOD;
        sm[SM_CUCL + (j * 66 + bl) * 2 + 0] = cu_g[(b0 + bl) * LOD + j];
        sm[SM_CUCL + (j * 66 + bl) * 2 + 1] = cl_g[(b0 + bl) * LOD + j];
        sm[SM_CS2 + j * 66 + bl] = 2.f * cs_g[(b0 + bl) * LOD + j];
    }
    for (int e = tid; e < BX * AD; e += NT) {
        int bl = e / AD, d = e % AD;
        sm[PW_ACT + d * 66 + bl] = action[(b0 + bl) * AD + d];
    }
    for (int e = tid; e < NB * LSD; e += NT) sm[PW_WC + e] = w_coef[e];
    for (int e = tid; e < HH * AD; e += NT)  sm[PW_W1 + e] = w_c1[e];
    for (int e = tid; e < LSD * HH; e += NT) sm[PW_W2 + e] = w_c2[e];
    if (tid < HH)  sm[PW_B1 + tid] = b_c1[tid];
    if (tid < LSD) sm[PW_B2 + tid] = b_c2[tid];
    if (tid < NB)  sm[PW_BC + tid] = b_coef[tid];
    if (tid < LSD) {
        float v = log_noise[tid];
        sm[SM_TC + tid] = (v < 0.f) ? expf(v) : v + 1.f;
    }
    __syncthreads();

    // ---- phase 1: logits + hidden layer ----
    for (int e = tid; e < NB * BX; e += NT) {      // 960 logits
        int k = e / BX, bl = e % BX;
        float lg = sm[PW_BC + k];
        #pragma unroll 4
        for (int d = 0; d < LSD; d++) {
            float pv = (d < LOD) ? sm[SM_MUML + (d * 66 + bl) * 2]
                                 : sm[SM_MUML + ((d - LOD) * 66 + bl) * 2 + 1];
            lg = fmaf(sm[PW_WC + k * LSD + d], pv, lg);
        }
        sm[PW_LG + k * 66 + bl] = lg;
    }
    for (int e = tid; e < HH * BX; e += NT) {      // 3840 hidden
        int i = e / BX, bl = e % BX;
        float hv = sm[PW_B1 + i];
        #pragma unroll
        for (int d = 0; d < AD; d++)
            hv = fmaf(sm[PW_W1 + i * AD + d], sm[PW_ACT + d * 66 + bl], hv);
        sm[PW_H + i * 66 + bl] = fmaxf(hv, 0.f);
    }
    __syncthreads();

    // ---- phase 2: softmax (-> SM_COEF) + control MLP (-> SM_CTL) ----
    if (tid < BX) {
        const int bl = tid;
        float mx = -1e30f;
        #pragma unroll
        for (int k = 0; k < NB; k++) mx = fmaxf(mx, sm[PW_LG + k * 66 + bl]);
        float ex[NB], sum = 0.f;
        #pragma unroll
        for (int k = 0; k < NB; k++) {
            ex[k] = expf(sm[PW_LG + k * 66 + bl] - mx);
            sum += ex[k];
        }
        float inv = 1.f / sum;
        #pragma unroll
        for (int k = 0; k < NB; k++) {
            float c = ex[k] * inv;
            ((u64*)(sm + SM_COEF))[k * BX + bl] = F2U(c, c);
        }
    }
    for (int e = tid; e < LSD * BX; e += NT) {     // 7680 ctl outputs
        int c = e / BX, bl = e % BX;
        float ctl = sm[PW_B2 + c];
        #pragma unroll 4
        for (int m = 0; m < HH; m++)
            ctl = fmaf(sm[PW_W2 + c * HH + m], sm[PW_H + m * 66 + bl], ctl);
        sm[SM_CTL + c * 66 + bl] = ctl;
    }
    __syncthreads();

    // ---- phase 3: wait for pack kernel, load tmb into smem ----
    cudaGridDependencySynchronize();
    {
        float4* t4 = (float4*)sm;
        for (int e = tid; e < LOD * 7 * NB; e += NT) t4[e] = g_tmb[e];
    }
    __syncthreads();

    // ---- phase 4: mix + combine (R4 hot loop, unchanged) ----
    const uint32_t sbase = (uint32_t)__cvta_generic_to_shared(sm);
    const uint32_t coefA = sbase + SM_COEF * 4 + (uint32_t)x * 8u;

    float res[5][5];

    #pragma unroll
    for (int t = 0; t < 5; t++) {
        const int i = y + BY * t;
        const uint32_t tmbRow = sbase + (uint32_t)(i * 7 * NB * 16);
        float nmu = 0.f, nml = 0.f, ncu = 0.f, ncl = 0.f, ncs = 0.f;
        {   // jj 0..3
            u64 aX[4], aY[4];
            mix_pass<0, 4>(tmbRow, coefA, aX, aY);
            #pragma unroll
            for (int jj = 0; jj < 4; jj++) {
                int jc = max(i + jj - 3, 0);
                combine(aX[jj], aY[jj], jj == 3, jc, x, sm, nmu, nml, ncu, ncl, ncs);
            }
        }
        {   // jj 4..6
            u64 aX[3], aY[3];
            mix_pass<4, 3>(tmbRow, coefA, aX, aY);
            #pragma unroll
            for (int jj = 0; jj < 3; jj++) {
                int jc = min(i + 1 + jj, LOD - 1);
                combine(aX[jj], aY[jj], false, jc, x, sm, nmu, nml, ncu, ncl, ncs);
            }
        }
        res[t][0] = nmu; res[t][1] = nml;
        res[t][2] = ncu; res[t][3] = ncl; res[t][4] = ncs;
    }

    __syncthreads();                 // all tmb/input reads complete
    #pragma unroll
    for (int t = 0; t < 5; t++) {    // stage into dead tmb region, stride 67
        int i = y + BY * t;
        sm[(i)        * 67 + x] = res[t][0];
        sm[(LOD + i)  * 67 + x] = res[t][1];
        sm[(120 + i)  * 67 + x] = res[t][2];
        sm[(180 + i)  * 67 + x] = res[t][3];
        sm[(240 + i)  * 67 + x] = res[t][4];
    }
    __syncthreads();

    // ---- phase 5: coalesced stores; fold in control + trans_cov ----
    for (int e = tid; e < BX * 300; e += NT) {
        int bl = e / 300, c = e % 300;
        float v = sm[c * 67 + bl];
        int bb = b0 + bl;
        if (c < 120) {
            v += sm[SM_CTL + c * 66 + bl];
            out[bb * 120 + c] = v;
        } else {
            if (c < 240) v += sm[SM_TC + (c - 120)];
            int blk = c / 60;        // 2, 3, 4
            out[NB_B * 60 * blk + bb * 60 + (c - blk * 60)] = v;
        }
    }
}

extern "C" void kernel_launch(void* const* d_in, const int* in_sizes, int n_in,
                              void* d_out, int out_size) {
    const float* post_mean = (const float*)d_in[0];
    const float* cu        = (const float*)d_in[1];
    const float* cl        = (const float*)d_in[2];
    const float* cs        = (const float*)d_in[3];
    const float* action    = (const float*)d_in[4];
    const float* tm11      = (const float*)d_in[5];
    const float* tm12      = (const float*)d_in[6];
    const float* tm21      = (const float*)d_in[7];
    const float* tm22      = (const float*)d_in[8];
    const float* log_noise = (const float*)d_in[9];
    const float* w_coef    = (const float*)d_in[10];
    const float* b_coef    = (const float*)d_in[11];
    const float* w_c1      = (const float*)d_in[12];
    const float* b_c1      = (const float*)d_in[13];
    const float* w_c2      = (const float*)d_in[14];
    const float* b_c2      = (const float*)d_in[15];
    float* out = (float*)d_out;

    static bool attr_done = false;
    if (!attr_done) {
        cudaFuncSetAttribute(acpredict_kernel,
            cudaFuncAttributeMaxDynamicSharedMemorySize, SM_FLOATS * 4);
        attr_done = true;
    }

    // primary: tiny tmb pack
    pack_kernel<<<13, 512>>>(tm11, tm12, tm21, tm22);

    // secondary: fused main kernel with PDL (preamble overlaps pack)
    cudaLaunchConfig_t cfg = {};
    cfg.gridDim = dim3(NB_B / BX);
    cfg.blockDim = dim3(BX, BY);
    cfg.dynamicSmemBytes = SM_FLOATS * 4;
    cfg.stream = 0;
    cudaLaunchAttribute at[1];
    at[0].id = cudaLaunchAttributeProgrammaticStreamSerialization;
    at[0].val.programmaticStreamSerializationAllowed = 1;
    cfg.attrs = at;
    cfg.numAttrs = 1;
    cudaLaunchKernelEx(&cfg, acpredict_kernel,
                       post_mean, cu, cl, cs, action, log_noise,
                       w_coef, b_coef, w_c1, b_c1, w_c2, b_c2, out);
}

// round 7
// speedup vs baseline: 1.1591x; 1.0815x over previous
#include <cuda_runtime.h>
#include <cstdint>

#define NB_B 8192
#define LOD 60
#define LSD 120
#define AD 10
#define NB 15
#define HH 60
#define BX 64
#define BY 12
#define NT 768

typedef unsigned long long u64;

// ---- device scratch ----
__device__ float4 g_tmb[LOD * 7 * NB];     // (t11,t21,t12,t22) banded, k fastest

#define FMA2(acc, a, b) asm("fma.rn.f32x2 %0, %1, %2, %0;" : "+l"(acc) : "l"(a), "l"(b))
__device__ __forceinline__ float2 U2F(u64 v){ float2 r; asm("mov.b64 {%0,%1},%2;" : "=f"(r.x), "=f"(r.y) : "l"(v)); return r; }
__device__ __forceinline__ u64 F2U(float x, float y){ u64 r; asm("mov.b64 %0,{%1,%2};" : "=l"(r) : "f"(x), "f"(y)); return r; }
__device__ __forceinline__ u64 LDS64(uint32_t a){ u64 r; asm("ld.shared.b64 %0,[%1];" : "=l"(r) : "r"(a)); return r; }

// ======================= pack kernel (tiny, overlapped via PDL) =======================
__global__ void __launch_bounds__(512) pack_kernel(
    const float* __restrict__ tm11, const float* __restrict__ tm12,
    const float* __restrict__ tm21, const float* __restrict__ tm22)
{
    int idx = blockIdx.x * 512 + threadIdx.x;
    if (idx >= LOD * 7 * NB) return;
    int k = idx % NB;
    int jj = (idx / NB) % 7;
    int i = idx / (NB * 7);
    int j = i + jj - 3;
    float4 v = make_float4(0.f, 0.f, 0.f, 0.f);
    if (j >= 0 && j < LOD) {
        int off = k * LOD * LOD + i * LOD + j;
        v.x = tm11[off]; v.y = tm21[off];
        v.z = tm12[off]; v.w = tm22[off];
    }
    g_tmb[idx] = v;
}

// ======================= fused main kernel =======================
// persistent smem regions (float offsets)
#define SM_TMB   0        // 25200 floats; prep scratch first, then tmb, then stage[300*67]
#define SM_MUML  25200    // float2[60][66] -> 7920
#define SM_CUCL  33120    // 7920
#define SM_CS2   41040    // 3960
#define SM_COEF  45000    // u64[15][64] -> 1920
#define SM_TC    46920    // 120
#define SM_CTL   47040    // u64[120][33*..] stored as float2 pairs -> 7920
#define SM_FLOATS 54960   // 219840 bytes

// prep scratch inside tmb region (dead before tmb load)
#define PW_WC   0         // packed float2[15][60] -> 1800
#define PW_W1   1800      // 600
#define PW_W2   2400      // duplicated float2[120][60] -> 14400
#define PW_B1   16800     // 60
#define PW_B2   16860     // 120
#define PW_BC   16980     // 15 (+pad)
#define PW_ACT  17000     // 10*66 = 660
#define PW_H    17660     // 60*66 = 3960
#define PW_LG   21620     // 15*66 = 990 -> 22610 < 25200

template<int J0, int JN>
__device__ __forceinline__ void mix_pass(
    uint32_t tmbRow, uint32_t coefA, u64* aX, u64* aY)
{
    #pragma unroll
    for (int jj = 0; jj < JN; jj++) { aX[jj] = 0; aY[jj] = 0; }
    #pragma unroll
    for (int k = 0; k < NB; k++) {
        u64 c2 = LDS64(coefA + (uint32_t)(k * 512));
        #pragma unroll
        for (int jj = 0; jj < JN; jj++) {
            u64 vX, vY;   // (t11,t21), (t12,t22) — warp-uniform broadcast
            asm("ld.shared.v2.u64 {%0,%1},[%2];"
                : "=l"(vX), "=l"(vY)
                : "r"(tmbRow + (uint32_t)(((J0 + jj) * NB + k) * 16)));
            FMA2(aX[jj], c2, vX);
            FMA2(aY[jj], c2, vY);
        }
    }
}

__device__ __forceinline__ void combine(
    u64 aXv, u64 aYv, bool diag, int jc, int x, const float* __restrict__ sm,
    float& nmu, float& nml, float& ncu, float& ncl, float& ncs)
{
    float2 X = U2F(aXv), Y = U2F(aYv);
    float t11 = X.x, t21 = X.y, t12 = Y.x, t22 = Y.y;
    if (diag) { t11 += 1.f; t22 += 1.f; }
    float2 mm = ((const float2*)(sm + SM_MUML))[jc * 66 + x];   // (mu, ml)
    float2 cc = ((const float2*)(sm + SM_CUCL))[jc * 66 + x];   // (cu, cl)
    float cs2 = sm[SM_CS2 + jc * 66 + x];
    nmu = fmaf(t11, mm.x, fmaf(t12, mm.y, nmu));
    nml = fmaf(t21, mm.x, fmaf(t22, mm.y, nml));
    ncu = fmaf(t11 * t11, cc.x, fmaf(t11 * t12, cs2, fmaf(t12 * t12, cc.y, ncu)));
    ncl = fmaf(t21 * t21, cc.x, fmaf(t21 * t22, cs2, fmaf(t22 * t22, cc.y, ncl)));
    ncs = fmaf(t21 * t11, cc.x,
          fmaf(0.5f * fmaf(t22, t11, t21 * t12), cs2,
          fmaf(t22 * t12, cc.y, ncs)));
}

__global__ void __launch_bounds__(NT, 1) acpredict_kernel(
    const float* __restrict__ post_mean, const float* __restrict__ cu_g,
    const float* __restrict__ cl_g, const float* __restrict__ cs_g,
    const float* __restrict__ action, const float* __restrict__ log_noise,
    const float* __restrict__ w_coef, const float* __restrict__ b_coef,
    const float* __restrict__ w_c1, const float* __restrict__ b_c1,
    const float* __restrict__ w_c2, const float* __restrict__ b_c2,
    float* __restrict__ out)
{
    extern __shared__ float sm[];
    const int x   = threadIdx.x;           // 0..63 : batch element
    const int y   = threadIdx.y;           // 0..11 : row group
    const int tid = y * BX + x;
    const int b0  = blockIdx.x * BX;

    // ---- phase 0: load inputs + prep weights (tmb region holds scratch) ----
    for (int e = tid; e < BX * LSD; e += NT) {
        int bl = e / LSD, d = e % LSD;
        float v = post_mean[(b0 + bl) * LSD + d];
        int j = (d < LOD) ? d : d - LOD;
        sm[SM_MUML + (j * 66 + bl) * 2 + (d < LOD ? 0 : 1)] = v;
    }
    for (int e = tid; e < BX * LOD; e += NT) {
        int bl = e / LOD, j = e % LOD;
        sm[SM_CUCL + (j * 66 + bl) * 2 + 0] = cu_g[(b0 + bl) * LOD + j];
        sm[SM_CUCL + (j * 66 + bl) * 2 + 1] = cl_g[(b0 + bl) * LOD + j];
        sm[SM_CS2 + j * 66 + bl] = 2.f * cs_g[(b0 + bl) * LOD + j];
    }
    for (int e = tid; e < BX * AD; e += NT) {
        int bl = e / AD, d = e % AD;
        sm[PW_ACT + d * 66 + bl] = action[(b0 + bl) * AD + d];
    }
    // w_coef packed as (w[k][j], w[k][j+60]) pairs
    for (int e = tid; e < NB * LSD; e += NT) {
        int k = e / LSD, d = e % LSD;
        int j = (d < LOD) ? d : d - LOD;
        sm[PW_WC + (k * LOD + j) * 2 + (d < LOD ? 0 : 1)] = w_coef[e];
    }
    for (int e = tid; e < HH * AD; e += NT)  sm[PW_W1 + e] = w_c1[e];
    // w_c2 duplicated as (w,w) pairs
    for (int e = tid; e < LSD * HH; e += NT) {
        float v = w_c2[e];
        ((u64*)(sm + PW_W2))[e] = F2U(v, v);
    }
    if (tid < HH)  sm[PW_B1 + tid] = b_c1[tid];
    if (tid < LSD) sm[PW_B2 + tid] = b_c2[tid];
    if (tid < NB)  sm[PW_BC + tid] = b_coef[tid];
    if (tid < LSD) {
        float v = log_noise[tid];
        sm[SM_TC + tid] = (v < 0.f) ? __expf(v) : v + 1.f;
    }
    __syncthreads();

    // ---- phase 1: logits (packed f32x2) + hidden layer ----
    for (int e = tid; e < NB * BX; e += NT) {
        int k = e / BX, bl = e % BX;
        u64 acc = 0;
        const u64* wcP = (const u64*)(sm + PW_WC) + k * LOD;     // warp-uniform
        const u64* mmP = (const u64*)(sm + SM_MUML);
        #pragma unroll 4
        for (int j = 0; j < LOD; j++)
            FMA2(acc, wcP[j], mmP[j * 66 + bl]);
        float2 p = U2F(acc);
        sm[PW_LG + k * 66 + bl] = p.x + p.y + sm[PW_BC + k];
    }
    for (int e = tid; e < HH * BX; e += NT) {
        int i = e / BX, bl = e % BX;
        float hv = sm[PW_B1 + i];
        #pragma unroll
        for (int d = 0; d < AD; d++)
            hv = fmaf(sm[PW_W1 + i * AD + d], sm[PW_ACT + d * 66 + bl], hv);
        sm[PW_H + i * 66 + bl] = fmaxf(hv, 0.f);
    }
    __syncthreads();

    // ---- phase 2: softmax (-> SM_COEF) + control MLP (packed, batch pairs) ----
    if (tid < BX) {
        const int bl = tid;
        float mx = -1e30f;
        #pragma unroll
        for (int k = 0; k < NB; k++) mx = fmaxf(mx, sm[PW_LG + k * 66 + bl]);
        float ex[NB], sum = 0.f;
        #pragma unroll
        for (int k = 0; k < NB; k++) {
            ex[k] = __expf(sm[PW_LG + k * 66 + bl] - mx);
            sum += ex[k];
        }
        float inv = 1.f / sum;
        #pragma unroll
        for (int k = 0; k < NB; k++) {
            float c = ex[k] * inv;
            ((u64*)(sm + SM_COEF))[k * BX + bl] = F2U(c, c);
        }
    }
    for (int e = tid; e < LSD * (BX / 2); e += NT) {   // 3840 batch-pair items
        int c = e / (BX / 2), blp = e % (BX / 2);
        float bb = sm[PW_B2 + c];
        u64 acc = F2U(bb, bb);
        const u64* w2P = (const u64*)(sm + PW_W2) + c * HH;      // warp-uniform dup pairs
        const u64* hP  = (const u64*)(sm + PW_H);                // h[m][2blp..2blp+1]
        #pragma unroll 4
        for (int m = 0; m < HH; m++)
            FMA2(acc, w2P[m], hP[m * 33 + blp]);
        ((u64*)(sm + SM_CTL))[c * 33 + blp] = acc;
    }
    __syncthreads();

    // ---- phase 3: wait for pack kernel, load tmb into smem ----
    cudaGridDependencySynchronize();
    {
        float4* t4 = (float4*)sm;
        for (int e = tid; e < LOD * 7 * NB; e += NT) t4[e] = g_tmb[e];
    }
    __syncthreads();

    // ---- phase 4: mix + combine (R4 hot loop, unchanged) ----
    const uint32_t sbase = (uint32_t)__cvta_generic_to_shared(sm);
    const uint32_t coefA = sbase + SM_COEF * 4 + (uint32_t)x * 8u;

    float res[5][5];

    #pragma unroll
    for (int t = 0; t < 5; t++) {
        const int i = y + BY * t;
        const uint32_t tmbRow = sbase + (uint32_t)(i * 7 * NB * 16);
        float nmu = 0.f, nml = 0.f, ncu = 0.f, ncl = 0.f, ncs = 0.f;
        {   // jj 0..3
            u64 aX[4], aY[4];
            mix_pass<0, 4>(tmbRow, coefA, aX, aY);
            #pragma unroll
            for (int jj = 0; jj < 4; jj++) {
                int jc = max(i + jj - 3, 0);
                combine(aX[jj], aY[jj], jj == 3, jc, x, sm, nmu, nml, ncu, ncl, ncs);
            }
        }
        {   // jj 4..6
            u64 aX[3], aY[3];
            mix_pass<4, 3>(tmbRow, coefA, aX, aY);
            #pragma unroll
            for (int jj = 0; jj < 3; jj++) {
                int jc = min(i + 1 + jj, LOD - 1);
                combine(aX[jj], aY[jj], false, jc, x, sm, nmu, nml, ncu, ncl, ncs);
            }
        }
        res[t][0] = nmu; res[t][1] = nml;
        res[t][2] = ncu; res[t][3] = ncl; res[t][4] = ncs;
    }

    __syncthreads();                 // all tmb/input reads complete
    #pragma unroll
    for (int t = 0; t < 5; t++) {    // stage into dead tmb region, stride 67
        int i = y + BY * t;
        sm[(i)        * 67 + x] = res[t][0];
        sm[(LOD + i)  * 67 + x] = res[t][1];
        sm[(120 + i)  * 67 + x] = res[t][2];
        sm[(180 + i)  * 67 + x] = res[t][3];
        sm[(240 + i)  * 67 + x] = res[t][4];
    }
    __syncthreads();

    // ---- phase 5: coalesced stores; fold in control + trans_cov ----
    for (int e = tid; e < BX * 300; e += NT) {
        int bl = e / 300, c = e % 300;
        float v = sm[c * 67 + bl];
        int bb = b0 + bl;
        if (c < 120) {
            v += sm[SM_CTL + c * 66 + bl];
            out[bb * 120 + c] = v;
        } else {
            if (c < 240) v += sm[SM_TC + (c - 120)];
            int blk = c / 60;        // 2, 3, 4
            out[NB_B * 60 * blk + bb * 60 + (c - blk * 60)] = v;
        }
    }
}

extern "C" void kernel_launch(void* const* d_in, const int* in_sizes, int n_in,
                              void* d_out, int out_size) {
    const float* post_mean = (const float*)d_in[0];
    const float* cu        = (const float*)d_in[1];
    const float* cl        = (const float*)d_in[2];
    const float* cs        = (const float*)d_in[3];
    const float* action    = (const float*)d_in[4];
    const float* tm11      = (const float*)d_in[5];
    const float* tm12      = (const float*)d_in[6];
    const float* tm21      = (const float*)d_in[7];
    const float* tm22      = (const float*)d_in[8];
    const float* log_noise = (const float*)d_in[9];
    const float* w_coef    = (const float*)d_in[10];
    const float* b_coef    = (const float*)d_in[11];
    const float* w_c1      = (const float*)d_in[12];
    const float* b_c1      = (const float*)d_in[13];
    const float* w_c2      = (const float*)d_in[14];
    const float* b_c2      = (const float*)d_in[15];
    float* out = (float*)d_out;

    static bool attr_done = false;
    if (!attr_done) {
        cudaFuncSetAttribute(acpredict_kernel,
            cudaFuncAttributeMaxDynamicSharedMemorySize, SM_FLOATS * 4);
        attr_done = true;
    }

    // primary: tiny tmb pack
    pack_kernel<<<13, 512>>>(tm11, tm12, tm21, tm22);

    // secondary: fused main kernel with PDL (preamble overlaps pack)
    cudaLaunchConfig_t cfg = {};
    cfg.gridDim = dim3(NB_B / BX);
    cfg.blockDim = dim3(BX, BY);
    cfg.dynamicSmemBytes = SM_FLOATS * 4;
    cfg.stream = 0;
    cudaLaunchAttribute at[1];
    at[0].id = cudaLaunchAttributeProgrammaticStreamSerialization;
    at[0].val.programmaticStreamSerializationAllowed = 1;
    cfg.attrs = at;
    cfg.numAttrs = 1;
    cudaLaunchKernelEx(&cfg, acpredict_kernel,
                       post_mean, cu, cl, cs, action, log_noise,
                       w_coef, b_coef, w_c1, b_c1, w_c2, b_c2, out);
}

// round 8
// speedup vs baseline: 1.1658x; 1.0058x over previous
#include <cuda_runtime.h>
#include <cstdint>

#define NB_B 8192
#define LOD 60
#define LSD 120
#define AD 10
#define NB 15
#define HH 60
#define BX 64
#define BY 12
#define NT 768

typedef unsigned long long u64;

// ---- device scratch ----
__device__ float4 g_tmb[LOD * 7 * NB];     // (t11,t21,t12,t22) banded, k fastest

#define FMA2(acc, a, b) asm("fma.rn.f32x2 %0, %1, %2, %0;" : "+l"(acc) : "l"(a), "l"(b))
__device__ __forceinline__ float2 U2F(u64 v){ float2 r; asm("mov.b64 {%0,%1},%2;" : "=f"(r.x), "=f"(r.y) : "l"(v)); return r; }
__device__ __forceinline__ u64 F2U(float x, float y){ u64 r; asm("mov.b64 %0,{%1,%2};" : "=l"(r) : "f"(x), "f"(y)); return r; }
__device__ __forceinline__ u64 LDS64(uint32_t a){ u64 r; asm("ld.shared.b64 %0,[%1];" : "=l"(r) : "r"(a)); return r; }

// ======================= pack kernel (tiny, overlapped via PDL) =======================
__global__ void __launch_bounds__(512) pack_kernel(
    const float* __restrict__ tm11, const float* __restrict__ tm12,
    const float* __restrict__ tm21, const float* __restrict__ tm22)
{
    int idx = blockIdx.x * 512 + threadIdx.x;
    if (idx >= LOD * 7 * NB) return;
    int k = idx % NB;
    int jj = (idx / NB) % 7;
    int i = idx / (NB * 7);
    int j = i + jj - 3;
    float4 v = make_float4(0.f, 0.f, 0.f, 0.f);
    if (j >= 0 && j < LOD) {
        int off = k * LOD * LOD + i * LOD + j;
        v.x = tm11[off]; v.y = tm21[off];
        v.z = tm12[off]; v.w = tm22[off];
    }
    g_tmb[idx] = v;
}

// ======================= fused main kernel =======================
// persistent smem regions (float offsets)
#define SM_TMB   0        // 25200 floats; prep scratch first, then tmb, then stage[300*67]
#define SM_MUML  25200    // float2[60][66] -> 7920
#define SM_CUCL  33120    // 7920
#define SM_CS2   41040    // 3960
#define SM_COEF  45000    // u64[15][64] -> 1920
#define SM_TC    46920    // 120
#define SM_CTL   47040    // float2 pairs -> 7920
#define SM_FLOATS 54960   // 219840 bytes

// prep scratch inside tmb region (dead before tmb load)
#define PW_WC   0         // packed float2[15][60] -> 1800
#define PW_W1   1800      // 600
#define PW_W2   2400      // duplicated float2[120][60] -> 14400
#define PW_B1   16800     // 60
#define PW_B2   16860     // 120
#define PW_BC   16980     // 15 (+pad)
#define PW_ACT  17000     // 10*66 = 660
#define PW_H    17660     // 60*66 = 3960
#define PW_LG   21620     // 15*66 = 990 -> 22610 < 25200

__device__ __forceinline__ void combine(
    u64 aXv, u64 aYv, bool diag, int jc, int x, const float* __restrict__ sm,
    float& nmu, float& nml, float& ncu, float& ncl, float& ncs)
{
    float2 X = U2F(aXv), Y = U2F(aYv);
    float t11 = X.x, t21 = X.y, t12 = Y.x, t22 = Y.y;
    if (diag) { t11 += 1.f; t22 += 1.f; }
    float2 mm = ((const float2*)(sm + SM_MUML))[jc * 66 + x];   // (mu, ml)
    float2 cc = ((const float2*)(sm + SM_CUCL))[jc * 66 + x];   // (cu, cl)
    float cs2 = sm[SM_CS2 + jc * 66 + x];
    nmu = fmaf(t11, mm.x, fmaf(t12, mm.y, nmu));
    nml = fmaf(t21, mm.x, fmaf(t22, mm.y, nml));
    ncu = fmaf(t11 * t11, cc.x, fmaf(t11 * t12, cs2, fmaf(t12 * t12, cc.y, ncu)));
    ncl = fmaf(t21 * t21, cc.x, fmaf(t21 * t22, cs2, fmaf(t22 * t22, cc.y, ncl)));
    ncs = fmaf(t21 * t11, cc.x,
          fmaf(0.5f * fmaf(t22, t11, t21 * t12), cs2,
          fmaf(t22 * t12, cc.y, ncs)));
}

__global__ void __launch_bounds__(NT, 1) acpredict_kernel(
    const float* __restrict__ post_mean, const float* __restrict__ cu_g,
    const float* __restrict__ cl_g, const float* __restrict__ cs_g,
    const float* __restrict__ action, const float* __restrict__ log_noise,
    const float* __restrict__ w_coef, const float* __restrict__ b_coef,
    const float* __restrict__ w_c1, const float* __restrict__ b_c1,
    const float* __restrict__ w_c2, const float* __restrict__ b_c2,
    float* __restrict__ out)
{
    extern __shared__ float sm[];
    const int x   = threadIdx.x;           // 0..63 : batch element
    const int y   = threadIdx.y;           // 0..11 : row group
    const int tid = y * BX + x;
    const int b0  = blockIdx.x * BX;

    // ---- phase 0: load inputs + prep weights (tmb region holds scratch) ----
    for (int e = tid; e < BX * LSD; e += NT) {
        int bl = e / LSD, d = e % LSD;
        float v = post_mean[(b0 + bl) * LSD + d];
        int j = (d < LOD) ? d : d - LOD;
        sm[SM_MUML + (j * 66 + bl) * 2 + (d < LOD ? 0 : 1)] = v;
    }
    for (int e = tid; e < BX * LOD; e += NT) {
        int bl = e / LOD, j = e % LOD;
        sm[SM_CUCL + (j * 66 + bl) * 2 + 0] = cu_g[(b0 + bl) * LOD + j];
        sm[SM_CUCL + (j * 66 + bl) * 2 + 1] = cl_g[(b0 + bl) * LOD + j];
        sm[SM_CS2 + j * 66 + bl] = 2.f * cs_g[(b0 + bl) * LOD + j];
    }
    for (int e = tid; e < BX * AD; e += NT) {
        int bl = e / AD, d = e % AD;
        sm[PW_ACT + d * 66 + bl] = action[(b0 + bl) * AD + d];
    }
    // w_coef packed as (w[k][j], w[k][j+60]) pairs
    for (int e = tid; e < NB * LSD; e += NT) {
        int k = e / LSD, d = e % LSD;
        int j = (d < LOD) ? d : d - LOD;
        sm[PW_WC + (k * LOD + j) * 2 + (d < LOD ? 0 : 1)] = w_coef[e];
    }
    for (int e = tid; e < HH * AD; e += NT)  sm[PW_W1 + e] = w_c1[e];
    // w_c2 duplicated as (w,w) pairs
    for (int e = tid; e < LSD * HH; e += NT) {
        float v = w_c2[e];
        ((u64*)(sm + PW_W2))[e] = F2U(v, v);
    }
    if (tid < HH)  sm[PW_B1 + tid] = b_c1[tid];
    if (tid < LSD) sm[PW_B2 + tid] = b_c2[tid];
    if (tid < NB)  sm[PW_BC + tid] = b_coef[tid];
    if (tid < LSD) {
        float v = log_noise[tid];
        sm[SM_TC + tid] = (v < 0.f) ? __expf(v) : v + 1.f;
    }
    __syncthreads();

    // ---- phase 1: logits (packed f32x2) + hidden layer ----
    for (int e = tid; e < NB * BX; e += NT) {
        int k = e / BX, bl = e % BX;
        u64 acc = 0;
        const u64* wcP = (const u64*)(sm + PW_WC) + k * LOD;     // warp-uniform
        const u64* mmP = (const u64*)(sm + SM_MUML);
        #pragma unroll 4
        for (int j = 0; j < LOD; j++)
            FMA2(acc, wcP[j], mmP[j * 66 + bl]);
        float2 p = U2F(acc);
        sm[PW_LG + k * 66 + bl] = p.x + p.y + sm[PW_BC + k];
    }
    for (int e = tid; e < HH * BX; e += NT) {
        int i = e / BX, bl = e % BX;
        float hv = sm[PW_B1 + i];
        #pragma unroll
        for (int d = 0; d < AD; d++)
            hv = fmaf(sm[PW_W1 + i * AD + d], sm[PW_ACT + d * 66 + bl], hv);
        sm[PW_H + i * 66 + bl] = fmaxf(hv, 0.f);
    }
    __syncthreads();

    // ---- phase 2: softmax (-> SM_COEF) + control MLP (packed, batch pairs) ----
    if (tid < BX) {
        const int bl = tid;
        float mx = -1e30f;
        #pragma unroll
        for (int k = 0; k < NB; k++) mx = fmaxf(mx, sm[PW_LG + k * 66 + bl]);
        float ex[NB], sum = 0.f;
        #pragma unroll
        for (int k = 0; k < NB; k++) {
            ex[k] = __expf(sm[PW_LG + k * 66 + bl] - mx);
            sum += ex[k];
        }
        float inv = 1.f / sum;
        #pragma unroll
        for (int k = 0; k < NB; k++) {
            float c = ex[k] * inv;
            ((u64*)(sm + SM_COEF))[k * BX + bl] = F2U(c, c);
        }
    }
    for (int e = tid; e < LSD * (BX / 2); e += NT) {   // 3840 batch-pair items
        int c = e / (BX / 2), blp = e % (BX / 2);
        float bb = sm[PW_B2 + c];
        u64 acc = F2U(bb, bb);
        const u64* w2P = (const u64*)(sm + PW_W2) + c * HH;      // warp-uniform dup pairs
        const u64* hP  = (const u64*)(sm + PW_H);                // h[m][2blp..2blp+1]
        #pragma unroll 4
        for (int m = 0; m < HH; m++)
            FMA2(acc, w2P[m], hP[m * 33 + blp]);
        ((u64*)(sm + SM_CTL))[c * 33 + blp] = acc;
    }
    __syncthreads();

    // ---- phase 3: wait for pack kernel, load tmb into smem ----
    cudaGridDependencySynchronize();
    {
        float4* t4 = (float4*)sm;
        for (int e = tid; e < LOD * 7 * NB; e += NT) t4[e] = g_tmb[e];
    }
    __syncthreads();

    // ---- phase 4: mix (single merged k-pass, 14 acc chains) + combine ----
    const uint32_t sbase = (uint32_t)__cvta_generic_to_shared(sm);
    const uint32_t coefA = sbase + SM_COEF * 4 + (uint32_t)x * 8u;

    float res[5][5];

    #pragma unroll
    for (int t = 0; t < 5; t++) {
        const int i = y + BY * t;
        const uint32_t tmbRow = sbase + (uint32_t)(i * 7 * NB * 16);

        u64 aX[7], aY[7];
        #pragma unroll
        for (int jj = 0; jj < 7; jj++) { aX[jj] = 0; aY[jj] = 0; }

        #pragma unroll
        for (int k = 0; k < NB; k++) {
            u64 c2 = LDS64(coefA + (uint32_t)(k * 512));
            #pragma unroll
            for (int jj = 0; jj < 7; jj++) {
                u64 vX, vY;   // (t11,t21), (t12,t22) — warp-uniform broadcast
                asm("ld.shared.v2.u64 {%0,%1},[%2];"
                    : "=l"(vX), "=l"(vY)
                    : "r"(tmbRow + (uint32_t)((jj * NB + k) * 16)));
                FMA2(aX[jj], c2, vX);
                FMA2(aY[jj], c2, vY);
            }
        }

        float nmu = 0.f, nml = 0.f, ncu = 0.f, ncl = 0.f, ncs = 0.f;
        #pragma unroll
        for (int jj = 0; jj < 7; jj++) {
            int jc = min(max(i + jj - 3, 0), LOD - 1);
            combine(aX[jj], aY[jj], jj == 3, jc, x, sm, nmu, nml, ncu, ncl, ncs);
        }
        res[t][0] = nmu; res[t][1] = nml;
        res[t][2] = ncu; res[t][3] = ncl; res[t][4] = ncs;
    }

    __syncthreads();                 // all tmb/input reads complete
    #pragma unroll
    for (int t = 0; t < 5; t++) {    // stage into dead tmb region, stride 67
        int i = y + BY * t;
        sm[(i)        * 67 + x] = res[t][0];
        sm[(LOD + i)  * 67 + x] = res[t][1];
        sm[(120 + i)  * 67 + x] = res[t][2];
        sm[(180 + i)  * 67 + x] = res[t][3];
        sm[(240 + i)  * 67 + x] = res[t][4];
    }
    __syncthreads();

    // ---- phase 5: coalesced stores; fold in control + trans_cov ----
    for (int e = tid; e < BX * 300; e += NT) {
        int bl = e / 300, c = e % 300;
        float v = sm[c * 67 + bl];
        int bb = b0 + bl;
        if (c < 120) {
            v += sm[SM_CTL + c * 66 + bl];
            out[bb * 120 + c] = v;
        } else {
            if (c < 240) v += sm[SM_TC + (c - 120)];
            int blk = c / 60;        // 2, 3, 4
            out[NB_B * 60 * blk + bb * 60 + (c - blk * 60)] = v;
        }
    }
}

extern "C" void kernel_launch(void* const* d_in, const int* in_sizes, int n_in,
                              void* d_out, int out_size) {
    const float* post_mean = (const float*)d_in[0];
    const float* cu        = (const float*)d_in[1];
    const float* cl        = (const float*)d_in[2];
    const float* cs        = (const float*)d_in[3];
    const float* action    = (const float*)d_in[4];
    const float* tm11      = (const float*)d_in[5];
    const float* tm12      = (const float*)d_in[6];
    const float* tm21      = (const float*)d_in[7];
    const float* tm22      = (const float*)d_in[8];
    const float* log_noise = (const float*)d_in[9];
    const float* w_coef    = (const float*)d_in[10];
    const float* b_coef    = (const float*)d_in[11];
    const float* w_c1      = (const float*)d_in[12];
    const float* b_c1      = (const float*)d_in[13];
    const float* w_c2      = (const float*)d_in[14];
    const float* b_c2      = (const float*)d_in[15];
    float* out = (float*)d_out;

    static bool attr_done = false;
    if (!attr_done) {
        cudaFuncSetAttribute(acpredict_kernel,
            cudaFuncAttributeMaxDynamicSharedMemorySize, SM_FLOATS * 4);
        attr_done = true;
    }

    // primary: tiny tmb pack
    pack_kernel<<<13, 512>>>(tm11, tm12, tm21, tm22);

    // secondary: fused main kernel with PDL (preamble overlaps pack)
    cudaLaunchConfig_t cfg = {};
    cfg.gridDim = dim3(NB_B / BX);
    cfg.blockDim = dim3(BX, BY);
    cfg.dynamicSmemBytes = SM_FLOATS * 4;
    cfg.stream = 0;
    cudaLaunchAttribute at[1];
    at[0].id = cudaLaunchAttributeProgrammaticStreamSerialization;
    at[0].val.programmaticStreamSerializationAllowed = 1;
    cfg.attrs = at;
    cfg.numAttrs = 1;
    cudaLaunchKernelEx(&cfg, acpredict_kernel,
                       post_mean, cu, cl, cs, action, log_noise,
                       w_coef, b_coef, w_c1, b_c1, w_c2, b_c2, out);
}